// round 9
// baseline (speedup 1.0000x reference)
#include <cuda_runtime.h>
#include <cuda_bf16.h>
#include <cstdint>

#define NTOK 16384
#define HDIM 4096
#define NEXP 64
#define BM   64
#define KC   64
#define STAGES 3
#define NCHUNK (HDIM / KC)           // 64
#define NKS    (HDIM / 16)           // 256 global k-steps
#define XS 68                        // x smem row stride (floats; 272B, 16B-aligned)
#define X_STAGE (BM * XS)            // 4352 floats = 17408B
#define WE 5                         // uint4 per expert per k-step (4 data + 1 pad)
#define W_STAGE_U4 (4 * NEXP * WE)   // 1280 uint4 = 20480B
#define SMEM_BYTES (STAGES * (X_STAGE * 4 + W_STAGE_U4 * 16))   // 3*37888 = 113664
#define DS 65                        // epilogue d-buffer row stride (floats)

#define FLT_MIN_NORMAL 1.17549435e-38f

// W packed in MMA-fragment order: [ks_g(256)][expert(64)][tg(4)] of
// uint4{bh0,bh1,bl0,bl1}; bh0 = bf16x2 cols (16ks+2tg, +1), bh1 = (+8,+9). 1MB.
__device__ uint4 g_w_pack[NKS * NEXP * 4];

__global__ void prep_w_kernel(const float* __restrict__ w) {
    int i = blockIdx.x * blockDim.x + threadIdx.x;   // 0..65535
    if (i >= NKS * NEXP * 4) return;
    int tg  = i & 3;
    int e   = (i >> 2) & 63;
    int ksg = i >> 8;
    int kb  = ksg * 16 + tg * 2;
    float v[4] = { w[(size_t)e * HDIM + kb],     w[(size_t)e * HDIM + kb + 1],
                   w[(size_t)e * HDIM + kb + 8], w[(size_t)e * HDIM + kb + 9] };
    __nv_bfloat16 h[4], l[4];
#pragma unroll
    for (int j = 0; j < 4; j++) {
        h[j] = __float2bfloat16_rn(v[j]);
        l[j] = __float2bfloat16_rn(v[j] - __bfloat162float(h[j]));
    }
    uint4 p;
    p.x = ((uint32_t)__bfloat16_as_ushort(h[1]) << 16) | __bfloat16_as_ushort(h[0]);
    p.y = ((uint32_t)__bfloat16_as_ushort(h[3]) << 16) | __bfloat16_as_ushort(h[2]);
    p.z = ((uint32_t)__bfloat16_as_ushort(l[1]) << 16) | __bfloat16_as_ushort(l[0]);
    p.w = ((uint32_t)__bfloat16_as_ushort(l[3]) << 16) | __bfloat16_as_ushort(l[2]);
    g_w_pack[i] = p;
}

__device__ __forceinline__ void mma_bf16(float* c, const uint32_t* a,
                                         uint32_t b0, uint32_t b1) {
    asm volatile(
        "mma.sync.aligned.m16n8k16.row.col.f32.bf16.bf16.f32 "
        "{%0,%1,%2,%3}, {%4,%5,%6,%7}, {%8,%9}, {%0,%1,%2,%3};\n"
        : "+f"(c[0]), "+f"(c[1]), "+f"(c[2]), "+f"(c[3])
        : "r"(a[0]), "r"(a[1]), "r"(a[2]), "r"(a[3]), "r"(b0), "r"(b1));
}

__device__ __forceinline__ void cvt_split(float2 f, uint32_t& hi, uint32_t& lo) {
    __nv_bfloat162 h = __floats2bfloat162_rn(f.x, f.y);
    float rx = f.x - __bfloat162float(h.x);
    float ry = f.y - __bfloat162float(h.y);
    __nv_bfloat162 l = __floats2bfloat162_rn(rx, ry);
    hi = *reinterpret_cast<uint32_t*>(&h);
    lo = *reinterpret_cast<uint32_t*>(&l);
}

__device__ __forceinline__ void cp16(void* smem_dst, const void* gmem_src) {
    uint32_t s = (uint32_t)__cvta_generic_to_shared(smem_dst);
    asm volatile("cp.async.cg.shared.global [%0], [%1], 16;\n" :: "r"(s), "l"(gmem_src));
}

__device__ __forceinline__ uint32_t f2sortable(float f) {
    uint32_t b = __float_as_uint(f);
    return b ^ (((int32_t)b >> 31) | 0x80000000u);
}
__device__ __forceinline__ float sortable2f(uint32_t k) {
    uint32_t b = (k & 0x80000000u) ? (k ^ 0x80000000u) : ~k;
    return __uint_as_float(b);
}

__global__ __launch_bounds__(256, 2)
void gate_kernel(const float* __restrict__ x,
                 const float* __restrict__ noise,
                 float* __restrict__ out) {
    extern __shared__ char smem[];
    float* xs = reinterpret_cast<float*>(smem);                       // [STAGES][BM][XS]
    uint4* wsm = reinterpret_cast<uint4*>(smem + STAGES * X_STAGE * 4); // [STAGES][4][NEXP][WE]

    const int tid  = threadIdx.x;
    const int warp = tid >> 5;
    const int lane = tid & 31;
    const int g    = lane >> 2;       // 0..7
    const int tg   = lane & 3;        // 0..3
    const int mt   = warp & 3;        // M-tile: rows mt*16..mt*16+15
    const int eh   = warp >> 2;       // expert half: experts eh*32..+31
    const int mBase = blockIdx.x * BM;

    float acc[4][4];
#pragma unroll
    for (int i = 0; i < 4; i++)
#pragma unroll
        for (int j = 0; j < 4; j++) acc[i][j] = 0.f;

    auto issue_stage = [&](int c, int slot) {
        const int k0 = c * KC;
        float* xb = xs + slot * X_STAGE;
#pragma unroll
        for (int i = 0; i < 4; i++) {                 // 64 rows x 16 granules = 1024
            int idx = tid + i * 256;
            int row = idx >> 4, c4 = idx & 15;
            cp16(xb + row * XS + c4 * 4,
                 x + (size_t)(mBase + row) * HDIM + k0 + c4 * 4);
        }
        uint4* wb = wsm + slot * W_STAGE_U4;
        const uint4* wsrc = g_w_pack + (size_t)c * 1024;  // [4][64][4] contiguous
#pragma unroll
        for (int i = 0; i < 4; i++) {                 // 1024 granules
            int idx = tid + i * 256;
            int ks = idx >> 8, e = (idx >> 2) & 63, t4 = idx & 3;
            cp16(wb + (ks * NEXP + e) * WE + t4, wsrc + idx);
        }
        asm volatile("cp.async.commit_group;\n" ::: "memory");
    };

    issue_stage(0, 0);
    issue_stage(1, 1);

    for (int c = 0; c < NCHUNK; c++) {
        asm volatile("cp.async.wait_group %0;\n" :: "n"(STAGES - 2) : "memory");
        __syncthreads();

        if (c + STAGES - 1 < NCHUNK)
            issue_stage(c + STAGES - 1, (c + STAGES - 1) % STAGES);
        else
            asm volatile("cp.async.commit_group;\n" ::: "memory");

        const int slot = c % STAGES;
        const float* xb = xs + slot * X_STAGE + mt * 16 * XS;
        const uint4* wb = wsm + slot * W_STAGE_U4;

#pragma unroll
        for (int ks = 0; ks < 4; ks++) {
            const int k0 = ks * 16;
            float2 f00 = *reinterpret_cast<const float2*>(xb + g * XS + k0 + tg * 2);
            float2 f01 = *reinterpret_cast<const float2*>(xb + g * XS + k0 + tg * 2 + 8);
            float2 f10 = *reinterpret_cast<const float2*>(xb + (g + 8) * XS + k0 + tg * 2);
            float2 f11 = *reinterpret_cast<const float2*>(xb + (g + 8) * XS + k0 + tg * 2 + 8);
            uint32_t ah[4], al[4];
            cvt_split(f00, ah[0], al[0]);
            cvt_split(f10, ah[1], al[1]);
            cvt_split(f01, ah[2], al[2]);
            cvt_split(f11, ah[3], al[3]);
#pragma unroll
            for (int nt = 0; nt < 4; nt++) {
                const int e = eh * 32 + nt * 8 + g;
                uint4 wv = wb[(ks * NEXP + e) * WE + tg];
                mma_bf16(acc[nt], ah, wv.x, wv.y);   // hi*hi
                mma_bf16(acc[nt], ah, wv.z, wv.w);   // hi*lo
                mma_bf16(acc[nt], al, wv.x, wv.y);   // lo*hi
            }
        }
    }

    // ---- epilogue ----
    // 1) dump logits to smem d-buffer [64 tokens][64 experts], stride DS=65
    __syncthreads();                  // all compute done; stage-0 x smem reusable
    float* dsm = xs;
#pragma unroll
    for (int nt = 0; nt < 4; nt++) {
        const int e0 = eh * 32 + nt * 8 + tg * 2;
        const int r0 = mt * 16 + g, r1 = r0 + 8;
        dsm[r0 * DS + e0]     = acc[nt][0];
        dsm[r0 * DS + e0 + 1] = acc[nt][1];
        dsm[r1 * DS + e0]     = acc[nt][2];
        dsm[r1 * DS + e0 + 1] = acc[nt][3];
    }
    __syncthreads();
    // 2) add noise (coalesced)
    for (int idx = tid; idx < BM * NEXP; idx += 256) {
        int row = idx >> 6, e = idx & 63;
        dsm[row * DS + e] += noise[(size_t)(mBase + row) * NEXP + e];
    }
    __syncthreads();

    // 3) per-token fp32 softmax + top-2 with FTZ/DAZ flush semantics
    //    (XLA:CPU ScopedFlushDenormal): score == 0 exactly when fl(exp(d))/s
    //    is subnormal, i.e. exp(d) < FLT_MIN * s; zeros tie -> lowest index.
    if (tid < BM) {
        const float* dr = dsm + tid * DS;
        float m = -3.4e38f;
#pragma unroll 8
        for (int e = 0; e < NEXP; e++) m = fmaxf(m, dr[e]);
        float s = 0.f;
#pragma unroll 8
        for (int e = 0; e < NEXP; e++) s += __expf(dr[e] - m);
        const float flushLim = FLT_MIN_NORMAL * s;

        unsigned long long k1 = 0ull, k2 = 0ull;
#pragma unroll 8
        for (int e = 0; e < NEXP; e++) {
            float d = dr[e] - m;
            float ed = __expf(d);
            uint32_t k32 = (ed < flushLim) ? 0u : f2sortable(d);
            unsigned long long key =
                ((unsigned long long)k32 << 32) | (unsigned long long)(64 - e);
            if (key > k1) { k2 = k1; k1 = key; }
            else if (key > k2) { k2 = key; }
        }

        const int n = mBase + tid;
        int i1 = 64 - (int)(k1 & 0xffffffffull);
        int i2 = 64 - (int)(k2 & 0xffffffffull);
        uint32_t k32_1 = (uint32_t)(k1 >> 32);
        uint32_t k32_2 = (uint32_t)(k2 >> 32);
        float inv = 1.0f / s;
        float w1 = (k32_1 == 0u) ? 0.f : __expf(sortable2f(k32_1)) * inv;
        float w2 = (k32_2 == 0u) ? 0.f : __expf(sortable2f(k32_2)) * inv;
        *reinterpret_cast<float2*>(out + 2 * n) = make_float2((float)i1, (float)i2);
        *reinterpret_cast<float2*>(out + 2 * NTOK + 2 * n) = make_float2(w1, w2);
    }
}

extern "C" void kernel_launch(void* const* d_in, const int* in_sizes, int n_in,
                              void* d_out, int out_size) {
    const float* x     = (const float*)d_in[0];  // hidden_states [4,4096,4096]
    const float* w     = (const float*)d_in[1];  // weight [64,4096]
    const float* noise = (const float*)d_in[2];  // noise [16384,64]
    float* out = (float*)d_out;

    cudaFuncSetAttribute(gate_kernel,
                         cudaFuncAttributeMaxDynamicSharedMemorySize, SMEM_BYTES);

    prep_w_kernel<<<(NKS * NEXP * 4 + 255) / 256, 256>>>(w);
    gate_kernel<<<NTOK / BM, 256, SMEM_BYTES>>>(x, noise, out);
}

// round 10
// speedup vs baseline: 1.1176x; 1.1176x over previous
#include <cuda_runtime.h>
#include <cuda_bf16.h>
#include <cstdint>

#define NTOK 16384
#define HDIM 4096
#define NEXP 64
#define BM   128
#define KC   64
#define NCHUNK (HDIM / KC)           // 64
#define NKS    (HDIM / 16)           // 256 global k-steps
#define XSB 72                       // x smem row stride (bf16; 144B -> LDSM conflict-free)
#define XH_STAGE (BM * XSB)          // 9216 bf16 = 18432B per stage per array
#define WE 5                         // uint4 per (ks,expert): 4 data + 1 pad
#define W_STAGE_U4 (4 * NEXP * WE)   // 1280 uint4 = 20480B per stage
#define SMEM_BYTES (2 * XH_STAGE * 2 * 2 + 2 * W_STAGE_U4 * 16)  // 73728 + 40960 = 114688

#define FLT_MIN_NORMAL 1.17549435e-38f

// W packed in MMA-fragment order: [ks_g(256)][expert(64)][tg(4)] of
// uint4{bh0,bh1,bl0,bl1}; bh0 = bf16x2 cols (16ks+2tg,+1), bh1 = (+8,+9). 1MB, L2-resident.
__device__ uint4 g_w_pack[NKS * NEXP * 4];

__global__ void prep_w_kernel(const float* __restrict__ w) {
    int i = blockIdx.x * blockDim.x + threadIdx.x;   // 0..65535
    if (i >= NKS * NEXP * 4) return;
    int tg  = i & 3;
    int e   = (i >> 2) & 63;
    int ksg = i >> 8;
    int kb  = ksg * 16 + tg * 2;
    float v[4] = { w[(size_t)e * HDIM + kb],     w[(size_t)e * HDIM + kb + 1],
                   w[(size_t)e * HDIM + kb + 8], w[(size_t)e * HDIM + kb + 9] };
    __nv_bfloat16 h[4], l[4];
#pragma unroll
    for (int j = 0; j < 4; j++) {
        h[j] = __float2bfloat16_rn(v[j]);
        l[j] = __float2bfloat16_rn(v[j] - __bfloat162float(h[j]));
    }
    uint4 p;
    p.x = ((uint32_t)__bfloat16_as_ushort(h[1]) << 16) | __bfloat16_as_ushort(h[0]);
    p.y = ((uint32_t)__bfloat16_as_ushort(h[3]) << 16) | __bfloat16_as_ushort(h[2]);
    p.z = ((uint32_t)__bfloat16_as_ushort(l[1]) << 16) | __bfloat16_as_ushort(l[0]);
    p.w = ((uint32_t)__bfloat16_as_ushort(l[3]) << 16) | __bfloat16_as_ushort(l[2]);
    g_w_pack[i] = p;
}

__device__ __forceinline__ void mma_bf16(float* c, const uint32_t* a,
                                         uint32_t b0, uint32_t b1) {
    asm volatile(
        "mma.sync.aligned.m16n8k16.row.col.f32.bf16.bf16.f32 "
        "{%0,%1,%2,%3}, {%4,%5,%6,%7}, {%8,%9}, {%0,%1,%2,%3};\n"
        : "+f"(c[0]), "+f"(c[1]), "+f"(c[2]), "+f"(c[3])
        : "r"(a[0]), "r"(a[1]), "r"(a[2]), "r"(a[3]), "r"(b0), "r"(b1));
}

__device__ __forceinline__ void ldsm4(uint32_t* r, uint32_t addr) {
    asm volatile("ldmatrix.sync.aligned.m8n8.x4.shared.b16 {%0,%1,%2,%3}, [%4];\n"
                 : "=r"(r[0]), "=r"(r[1]), "=r"(r[2]), "=r"(r[3]) : "r"(addr));
}

__device__ __forceinline__ void cp16(void* smem_dst, const void* gmem_src) {
    uint32_t s = (uint32_t)__cvta_generic_to_shared(smem_dst);
    asm volatile("cp.async.cg.shared.global [%0], [%1], 16;\n" :: "r"(s), "l"(gmem_src));
}

__device__ __forceinline__ uint32_t f2sortable(float f) {
    uint32_t b = __float_as_uint(f);
    return b ^ (((int32_t)b >> 31) | 0x80000000u);
}
__device__ __forceinline__ float sortable2f(uint32_t k) {
    uint32_t b = (k & 0x80000000u) ? (k ^ 0x80000000u) : ~k;
    return __uint_as_float(b);
}

__global__ __launch_bounds__(256, 1)
void gate_kernel(const float* __restrict__ x,
                 const float* __restrict__ noise,
                 float* __restrict__ out) {
    extern __shared__ char smem[];
    __nv_bfloat16* xh = reinterpret_cast<__nv_bfloat16*>(smem);          // [2][BM][XSB]
    __nv_bfloat16* xl = xh + 2 * XH_STAGE;                                // [2][BM][XSB]
    uint4* wsm = reinterpret_cast<uint4*>(smem + 2 * XH_STAGE * 2 * 2);   // [2][4][64][WE]

    const int tid  = threadIdx.x;
    const int warp = tid >> 5;
    const int lane = tid & 31;
    const int g    = lane >> 2;
    const int tg   = lane & 3;
    const int mBase = blockIdx.x * BM;

    float acc[8][4];
#pragma unroll
    for (int i = 0; i < 8; i++)
#pragma unroll
        for (int j = 0; j < 4; j++) acc[i][j] = 0.f;

    float4 xr[8];

    // LDSM source lane mapping: rows warp*16+(lane&15), col block +8 for lanes>=16
    const int lrow  = warp * 16 + (lane & 15);
    const int lcol8 = (lane >> 4) * 8;
    const uint32_t xh_u32 = (uint32_t)__cvta_generic_to_shared(xh);
    const uint32_t xl_u32 = (uint32_t)__cvta_generic_to_shared(xl);

    auto ldg_x = [&](int c) {
        const int k0 = c * KC;
#pragma unroll
        for (int i = 0; i < 8; i++) {              // 128 rows x 16 float4 = 2048 granules
            int idx = tid + i * 256;
            int row = idx >> 4, c4 = idx & 15;
            xr[i] = *reinterpret_cast<const float4*>(
                x + (size_t)(mBase + row) * HDIM + k0 + c4 * 4);
        }
    };
    auto issue_w = [&](int c, int slot) {
        uint4* wb = wsm + slot * W_STAGE_U4;
        const uint4* wsrc = g_w_pack + (size_t)c * 1024;   // [4][64][4] contiguous
#pragma unroll
        for (int i = 0; i < 4; i++) {
            int idx = tid + i * 256;
            int ks = idx >> 8, e = (idx >> 2) & 63, t4 = idx & 3;
            cp16(wb + (ks * NEXP + e) * WE + t4, wsrc + idx);
        }
        asm volatile("cp.async.commit_group;\n" ::: "memory");
    };
    auto store_x = [&](int slot) {
        __nv_bfloat16* xhb = xh + slot * XH_STAGE;
        __nv_bfloat16* xlb = xl + slot * XH_STAGE;
#pragma unroll
        for (int i = 0; i < 8; i++) {
            int idx = tid + i * 256;
            int row = idx >> 4, c4 = idx & 15;
            float4 f = xr[i];
            __nv_bfloat162 h01 = __floats2bfloat162_rn(f.x, f.y);
            __nv_bfloat162 h23 = __floats2bfloat162_rn(f.z, f.w);
            __nv_bfloat162 l01 = __floats2bfloat162_rn(f.x - __bfloat162float(h01.x),
                                                       f.y - __bfloat162float(h01.y));
            __nv_bfloat162 l23 = __floats2bfloat162_rn(f.z - __bfloat162float(h23.x),
                                                       f.w - __bfloat162float(h23.y));
            uint2 ph = make_uint2(*reinterpret_cast<uint32_t*>(&h01),
                                  *reinterpret_cast<uint32_t*>(&h23));
            uint2 pl = make_uint2(*reinterpret_cast<uint32_t*>(&l01),
                                  *reinterpret_cast<uint32_t*>(&l23));
            *reinterpret_cast<uint2*>(xhb + row * XSB + c4 * 4) = ph;
            *reinterpret_cast<uint2*>(xlb + row * XSB + c4 * 4) = pl;
        }
    };

    // prologue: chunk 0 fully staged
    ldg_x(0);
    issue_w(0, 0);
    store_x(0);
    asm volatile("cp.async.wait_group 0;\n" ::: "memory");
    __syncthreads();

    for (int c = 0; c < NCHUNK; c++) {
        const int slot = c & 1;
        if (c + 1 < NCHUNK) {
            ldg_x(c + 1);              // LDGs fly during compute
            issue_w(c + 1, slot ^ 1);  // cp.async flies during compute
        }

        // ---- compute chunk c ----
        const uint32_t xh_addr = xh_u32 + (slot * XH_STAGE + lrow * XSB) * 2;
        const uint32_t xl_addr = xl_u32 + (slot * XH_STAGE + lrow * XSB) * 2;
        const uint4* wb = wsm + slot * W_STAGE_U4;
#pragma unroll
        for (int ks = 0; ks < 4; ks++) {
            const uint32_t coff = (ks * 16 + lcol8) * 2;
            uint32_t ah[4], al[4];
            ldsm4(ah, xh_addr + coff);
            ldsm4(al, xl_addr + coff);
#pragma unroll
            for (int nt = 0; nt < 8; nt++) {
                const int e = nt * 8 + g;
                uint4 wv = wb[(ks * NEXP + e) * WE + tg];
                mma_bf16(acc[nt], ah, wv.x, wv.y);   // hi*hi
                mma_bf16(acc[nt], ah, wv.z, wv.w);   // hi*lo
                mma_bf16(acc[nt], al, wv.x, wv.y);   // lo*hi
            }
        }
        __syncthreads();                  // everyone done reading slot^1-adjacent data
        if (c + 1 < NCHUNK) {
            store_x(slot ^ 1);            // stage next x (regs -> smem, converted)
            asm volatile("cp.async.wait_group 0;\n" ::: "memory");
            __syncthreads();              // next chunk (x + W) visible
        }
    }

    // ---- epilogue: noise add, then FTZ/DAZ softmax semantics (XLA:CPU
    //      ScopedFlushDenormal): score flushes to exactly 0 when fl(exp(d))/s
    //      is subnormal, i.e. exp(d) < FLT_MIN * s. Flushed experts tie at 0
    //      -> lowest index wins (jax top_k). Above flush line: order of d.
    const int n0 = mBase + warp * 16 + g;
    const int n1 = n0 + 8;
#pragma unroll
    for (int nt = 0; nt < 8; nt++) {
        const int e = nt * 8 + tg * 2;
        float2 nz0 = *reinterpret_cast<const float2*>(noise + (size_t)n0 * NEXP + e);
        float2 nz1 = *reinterpret_cast<const float2*>(noise + (size_t)n1 * NEXP + e);
        acc[nt][0] += nz0.x; acc[nt][1] += nz0.y;
        acc[nt][2] += nz1.x; acc[nt][3] += nz1.y;
    }

#pragma unroll
    for (int r = 0; r < 2; r++) {
        float m = -3.4e38f;
#pragma unroll
        for (int nt = 0; nt < 8; nt++) {
#pragma unroll
            for (int jj = 0; jj < 2; jj++)
                m = fmaxf(m, acc[nt][r * 2 + jj]);
        }
#pragma unroll
        for (int mm = 1; mm <= 2; mm <<= 1)
            m = fmaxf(m, __shfl_xor_sync(0xffffffffu, m, mm));

        float dv[16];
        float s = 0.f;
#pragma unroll
        for (int nt = 0; nt < 8; nt++) {
#pragma unroll
            for (int jj = 0; jj < 2; jj++) {
                float d = acc[nt][r * 2 + jj] - m;
                dv[nt * 2 + jj] = d;
                s += __expf(d);
            }
        }
#pragma unroll
        for (int mm = 1; mm <= 2; mm <<= 1)
            s += __shfl_xor_sync(0xffffffffu, s, mm);

        const float flushLim = FLT_MIN_NORMAL * s;

        unsigned long long k1 = 0ull, k2 = 0ull;
#pragma unroll
        for (int nt = 0; nt < 8; nt++) {
#pragma unroll
            for (int jj = 0; jj < 2; jj++) {
                float d = dv[nt * 2 + jj];
                int   e = nt * 8 + tg * 2 + jj;
                float ed = __expf(d);
                uint32_t k32 = (ed < flushLim) ? 0u : f2sortable(d);
                unsigned long long key =
                    ((unsigned long long)k32 << 32) | (unsigned long long)(64 - e);
                if (key > k1) { k2 = k1; k1 = key; }
                else if (key > k2) { k2 = key; }
            }
        }
#pragma unroll
        for (int mm = 1; mm <= 2; mm <<= 1) {
            unsigned long long o1 = __shfl_xor_sync(0xffffffffu, k1, mm);
            unsigned long long o2 = __shfl_xor_sync(0xffffffffu, k2, mm);
            if (o1 > k1) { k2 = k1; k1 = o1; } else if (o1 > k2) { k2 = o1; }
            if (o2 > k1) { k2 = k1; k1 = o2; } else if (o2 > k2) { k2 = o2; }
        }

        if (tg == 0) {
            const int n = (r == 0) ? n0 : n1;
            int i1 = 64 - (int)(k1 & 0xffffffffull);
            int i2 = 64 - (int)(k2 & 0xffffffffull);
            uint32_t k32_1 = (uint32_t)(k1 >> 32);
            uint32_t k32_2 = (uint32_t)(k2 >> 32);
            float inv = 1.0f / s;
            float w1 = (k32_1 == 0u) ? 0.f : __expf(sortable2f(k32_1)) * inv;
            float w2 = (k32_2 == 0u) ? 0.f : __expf(sortable2f(k32_2)) * inv;
            out[2 * n + 0] = (float)i1;
            out[2 * n + 1] = (float)i2;
            out[2 * NTOK + 2 * n + 0] = w1;
            out[2 * NTOK + 2 * n + 1] = w2;
        }
    }
}

extern "C" void kernel_launch(void* const* d_in, const int* in_sizes, int n_in,
                              void* d_out, int out_size) {
    const float* x     = (const float*)d_in[0];  // hidden_states [4,4096,4096]
    const float* w     = (const float*)d_in[1];  // weight [64,4096]
    const float* noise = (const float*)d_in[2];  // noise [16384,64]
    float* out = (float*)d_out;

    cudaFuncSetAttribute(gate_kernel,
                         cudaFuncAttributeMaxDynamicSharedMemorySize, SMEM_BYTES);

    prep_w_kernel<<<(NKS * NEXP * 4 + 255) / 256, 256>>>(w);
    gate_kernel<<<NTOK / BM, 256, SMEM_BYTES>>>(x, noise, out);
}

// round 11
// speedup vs baseline: 1.4260x; 1.2759x over previous
#include <cuda_runtime.h>
#include <cuda_bf16.h>
#include <cstdint>

#define NTOK 16384
#define HDIM 4096
#define NEXP 64
#define BM   64
#define KC   64
#define XS   (KC + 8)   // x smem row stride (floats)  = 72
#define WS   (KC + 8)   // w smem row stride (bf16)    = 72
#define NCHUNK (HDIM / KC)      // 64
#define SMEM_X_BYTES (2 * BM * XS * 4)            // 36864
#define SMEM_W_BYTES (2 * NEXP * WS * 2)          // 18432 per array
#define SMEM_BYTES   (SMEM_X_BYTES + 2 * SMEM_W_BYTES)  // 73728

#define FLT_MIN_NORMAL 1.17549435e-38f

// Pre-split W (fp32 -> bf16 hi + bf16 lo), 1 MB total, L2-resident.
__device__ __nv_bfloat16 g_w_hi[NEXP * HDIM];
__device__ __nv_bfloat16 g_w_lo[NEXP * HDIM];

__global__ void prep_w_kernel(const float* __restrict__ w) {
    int i = blockIdx.x * blockDim.x + threadIdx.x;
    if (i < NEXP * HDIM) {
        float v = w[i];
        __nv_bfloat16 hi = __float2bfloat16_rn(v);
        float r = v - __bfloat162float(hi);
        g_w_hi[i] = hi;
        g_w_lo[i] = __float2bfloat16_rn(r);
    }
}

__device__ __forceinline__ void mma_bf16(float* c, const uint32_t* a,
                                         uint32_t b0, uint32_t b1) {
    asm volatile(
        "mma.sync.aligned.m16n8k16.row.col.f32.bf16.bf16.f32 "
        "{%0,%1,%2,%3}, {%4,%5,%6,%7}, {%8,%9}, {%0,%1,%2,%3};\n"
        : "+f"(c[0]), "+f"(c[1]), "+f"(c[2]), "+f"(c[3])
        : "r"(a[0]), "r"(a[1]), "r"(a[2]), "r"(a[3]), "r"(b0), "r"(b1));
}

__device__ __forceinline__ void cvt_split(float2 f, uint32_t& hi, uint32_t& lo) {
    __nv_bfloat162 h = __floats2bfloat162_rn(f.x, f.y);
    float rx = f.x - __bfloat162float(h.x);
    float ry = f.y - __bfloat162float(h.y);
    __nv_bfloat162 l = __floats2bfloat162_rn(rx, ry);
    hi = *reinterpret_cast<uint32_t*>(&h);
    lo = *reinterpret_cast<uint32_t*>(&l);
}

__device__ __forceinline__ uint32_t f2sortable(float f) {
    uint32_t b = __float_as_uint(f);
    return b ^ (((int32_t)b >> 31) | 0x80000000u);
}
__device__ __forceinline__ float sortable2f(uint32_t k) {
    uint32_t b = (k & 0x80000000u) ? (k ^ 0x80000000u) : ~k;
    return __uint_as_float(b);
}

__global__ __launch_bounds__(128, 2)
void gate_kernel(const float* __restrict__ x,
                 const float* __restrict__ noise,
                 float* __restrict__ out) {
    extern __shared__ char smem[];
    float* xs = reinterpret_cast<float*>(smem);                       // [2][BM][XS]
    __nv_bfloat16* wh = reinterpret_cast<__nv_bfloat16*>(smem + SMEM_X_BYTES); // [2][NEXP][WS]
    __nv_bfloat16* wl = wh + 2 * NEXP * WS;

    const int tid  = threadIdx.x;
    const int warp = tid >> 5;    // 0..3
    const int lane = tid & 31;
    const int g    = lane >> 2;   // group id (row within 8)
    const int tg   = lane & 3;    // thread in group
    const int mBase = blockIdx.x * BM;

    float acc[8][4];
#pragma unroll
    for (int i = 0; i < 8; i++)
#pragma unroll
        for (int j = 0; j < 4; j++) acc[i][j] = 0.f;

    float4 xr[8];
    uint4  wrh[4], wrl[4];

    // ---- prefetch helpers (reg-staged, R7-proven structure) ----
    auto load_regs = [&](int k0) {
#pragma unroll
        for (int i = 0; i < 8; i++) {                 // 64 rows x 16 float4 = 1024
            int idx = tid + i * 128;
            int row = idx >> 4, c4 = idx & 15;
            xr[i] = *reinterpret_cast<const float4*>(
                x + (size_t)(mBase + row) * HDIM + k0 + c4 * 4);
        }
#pragma unroll
        for (int i = 0; i < 4; i++) {                 // 64 rows x 8 granules = 512
            int idx = tid + i * 128;
            int row = idx >> 3, q = idx & 7;
            wrh[i] = *reinterpret_cast<const uint4*>(
                g_w_hi + (size_t)row * HDIM + k0 + q * 8);
            wrl[i] = *reinterpret_cast<const uint4*>(
                g_w_lo + (size_t)row * HDIM + k0 + q * 8);
        }
    };
    auto store_regs = [&](int buf) {
        float* xb = xs + buf * BM * XS;
#pragma unroll
        for (int i = 0; i < 8; i++) {
            int idx = tid + i * 128;
            int row = idx >> 4, c4 = idx & 15;
            *reinterpret_cast<float4*>(xb + row * XS + c4 * 4) = xr[i];
        }
        __nv_bfloat16* whb = wh + buf * NEXP * WS;
        __nv_bfloat16* wlb = wl + buf * NEXP * WS;
#pragma unroll
        for (int i = 0; i < 4; i++) {
            int idx = tid + i * 128;
            int row = idx >> 3, q = idx & 7;
            *reinterpret_cast<uint4*>(whb + row * WS + q * 8) = wrh[i];
            *reinterpret_cast<uint4*>(wlb + row * WS + q * 8) = wrl[i];
        }
    };

    // prologue: chunk 0
    load_regs(0);
    store_regs(0);
    __syncthreads();

    for (int c = 0; c < NCHUNK; c++) {
        const int buf = c & 1;
        if (c + 1 < NCHUNK) load_regs((c + 1) * KC);

        const float* xb = xs + buf * BM * XS + warp * 16 * XS;
        const __nv_bfloat16* whb = wh + buf * NEXP * WS;
        const __nv_bfloat16* wlb = wl + buf * NEXP * WS;

#pragma unroll
        for (int ks = 0; ks < KC / 16; ks++) {
            const int k0 = ks * 16;
            float2 f00 = *reinterpret_cast<const float2*>(xb + g * XS + k0 + tg * 2);
            float2 f01 = *reinterpret_cast<const float2*>(xb + g * XS + k0 + tg * 2 + 8);
            float2 f10 = *reinterpret_cast<const float2*>(xb + (g + 8) * XS + k0 + tg * 2);
            float2 f11 = *reinterpret_cast<const float2*>(xb + (g + 8) * XS + k0 + tg * 2 + 8);
            uint32_t ah[4], al[4];
            cvt_split(f00, ah[0], al[0]);
            cvt_split(f10, ah[1], al[1]);
            cvt_split(f01, ah[2], al[2]);
            cvt_split(f11, ah[3], al[3]);
#pragma unroll
            for (int nt = 0; nt < 8; nt++) {
                const int e = nt * 8 + g;
                uint32_t bh0 = *reinterpret_cast<const uint32_t*>(whb + e * WS + k0 + tg * 2);
                uint32_t bh1 = *reinterpret_cast<const uint32_t*>(whb + e * WS + k0 + tg * 2 + 8);
                uint32_t bl0 = *reinterpret_cast<const uint32_t*>(wlb + e * WS + k0 + tg * 2);
                uint32_t bl1 = *reinterpret_cast<const uint32_t*>(wlb + e * WS + k0 + tg * 2 + 8);
                mma_bf16(acc[nt], ah, bh0, bh1);   // hi*hi
                mma_bf16(acc[nt], ah, bl0, bl1);   // hi*lo
                mma_bf16(acc[nt], al, bh0, bh1);   // lo*hi
            }
        }
        __syncthreads();
        if (c + 1 < NCHUNK) {
            store_regs(buf ^ 1);
            __syncthreads();
        }
    }

    // ---- epilogue: noise add, then FTZ/DAZ softmax semantics (XLA:CPU
    //      ScopedFlushDenormal): score flushes to exactly 0 when fl(exp(d))/s
    //      is subnormal, i.e. exp(d) < FLT_MIN * s. Flushed experts tie at 0
    //      -> lowest index wins (jax top_k). Above flush line: order of d.
    const int n0 = mBase + warp * 16 + g;
    const int n1 = n0 + 8;
#pragma unroll
    for (int nt = 0; nt < 8; nt++) {
        const int e = nt * 8 + tg * 2;
        float2 nz0 = *reinterpret_cast<const float2*>(noise + (size_t)n0 * NEXP + e);
        float2 nz1 = *reinterpret_cast<const float2*>(noise + (size_t)n1 * NEXP + e);
        acc[nt][0] += nz0.x; acc[nt][1] += nz0.y;
        acc[nt][2] += nz1.x; acc[nt][3] += nz1.y;
    }

#pragma unroll
    for (int r = 0; r < 2; r++) {
        float m = -3.4e38f;
#pragma unroll
        for (int nt = 0; nt < 8; nt++) {
#pragma unroll
            for (int jj = 0; jj < 2; jj++)
                m = fmaxf(m, acc[nt][r * 2 + jj]);
        }
#pragma unroll
        for (int mm = 1; mm <= 2; mm <<= 1)
            m = fmaxf(m, __shfl_xor_sync(0xffffffffu, m, mm));

        float dv[16];
        float s = 0.f;
#pragma unroll
        for (int nt = 0; nt < 8; nt++) {
#pragma unroll
            for (int jj = 0; jj < 2; jj++) {
                float d = acc[nt][r * 2 + jj] - m;
                dv[nt * 2 + jj] = d;
                s += __expf(d);
            }
        }
#pragma unroll
        for (int mm = 1; mm <= 2; mm <<= 1)
            s += __shfl_xor_sync(0xffffffffu, s, mm);

        const float flushLim = FLT_MIN_NORMAL * s;

        unsigned long long k1 = 0ull, k2 = 0ull;
#pragma unroll
        for (int nt = 0; nt < 8; nt++) {
#pragma unroll
            for (int jj = 0; jj < 2; jj++) {
                float d = dv[nt * 2 + jj];
                int   e = nt * 8 + tg * 2 + jj;
                float ed = __expf(d);
                uint32_t k32 = (ed < flushLim) ? 0u : f2sortable(d);
                unsigned long long key =
                    ((unsigned long long)k32 << 32) | (unsigned long long)(64 - e);
                if (key > k1) { k2 = k1; k1 = key; }
                else if (key > k2) { k2 = key; }
            }
        }
#pragma unroll
        for (int mm = 1; mm <= 2; mm <<= 1) {
            unsigned long long o1 = __shfl_xor_sync(0xffffffffu, k1, mm);
            unsigned long long o2 = __shfl_xor_sync(0xffffffffu, k2, mm);
            if (o1 > k1) { k2 = k1; k1 = o1; } else if (o1 > k2) { k2 = o1; }
            if (o2 > k1) { k2 = k1; k1 = o2; } else if (o2 > k2) { k2 = o2; }
        }

        if (tg == 0) {
            const int n = (r == 0) ? n0 : n1;
            int i1 = 64 - (int)(k1 & 0xffffffffull);
            int i2 = 64 - (int)(k2 & 0xffffffffull);
            uint32_t k32_1 = (uint32_t)(k1 >> 32);
            uint32_t k32_2 = (uint32_t)(k2 >> 32);
            float inv = 1.0f / s;
            float w1 = (k32_1 == 0u) ? 0.f : __expf(sortable2f(k32_1)) * inv;
            float w2 = (k32_2 == 0u) ? 0.f : __expf(sortable2f(k32_2)) * inv;
            out[2 * n + 0] = (float)i1;
            out[2 * n + 1] = (float)i2;
            out[2 * NTOK + 2 * n + 0] = w1;
            out[2 * NTOK + 2 * n + 1] = w2;
        }
    }
}

extern "C" void kernel_launch(void* const* d_in, const int* in_sizes, int n_in,
                              void* d_out, int out_size) {
    const float* x     = (const float*)d_in[0];  // hidden_states [4,4096,4096]
    const float* w     = (const float*)d_in[1];  // weight [64,4096]
    const float* noise = (const float*)d_in[2];  // noise [16384,64]
    float* out = (float*)d_out;

    cudaFuncSetAttribute(gate_kernel,
                         cudaFuncAttributeMaxDynamicSharedMemorySize, SMEM_BYTES);

    prep_w_kernel<<<(NEXP * HDIM + 255) / 256, 256>>>(w);
    gate_kernel<<<NTOK / BM, 128, SMEM_BYTES>>>(x, noise, out);
}